// round 11
// baseline (speedup 1.0000x reference)
#include <cuda_runtime.h>
#include <cuda_bf16.h>
#include <math.h>
#include <stdint.h>

#define HID 1024
#define NH  16
#define HD  64
#define NB  4
#define SQL 1024
#define SKV 2048

// ---------------- scratch (__device__ globals; no allocs allowed) ----------
__device__ __nv_bfloat16 s_xq [(size_t)2 * NB * SQL * HID];
__device__ __nv_bfloat16 s_xkv[(size_t)2 * NB * SKV * HID];
__device__ __nv_bfloat16 s_wq [(size_t)2 * HID * HID];
__device__ __nv_bfloat16 s_wkv[(size_t)2 * 2 * HID * HID];
__device__ __nv_bfloat16 s_wo [(size_t)2 * HID * HID];
__device__ __nv_bfloat16 s_x  [(size_t)2 * NB * SQL * HID];
__device__ __nv_bfloat16 s_qa [(size_t)2 * NB * SQL * HID];
__device__ __nv_bfloat16 s_kva[(size_t)2 * NB * SKV * 2 * HID];

// ---------------------------------------------------------------------------
static __device__ __forceinline__ uint32_t smem_u32(const void* p) {
    uint32_t a;
    asm("{ .reg .u64 t; cvta.to.shared.u64 t, %1; cvt.u32.u64 %0, t; }"
        : "=r"(a) : "l"(p));
    return a;
}

#define CPA16(dst, src) \
    asm volatile("cp.async.cg.shared.global [%0], [%1], 16;" \
                 :: "r"(dst), "l"(src) : "memory")
#define CPA_COMMIT() asm volatile("cp.async.commit_group;" ::: "memory")
#define CPA_WAIT1()  asm volatile("cp.async.wait_group 1;" ::: "memory")
#define CPA_WAIT0()  asm volatile("cp.async.wait_group 0;" ::: "memory")

// split barrier (named): count 256 = 128 arrives (prev iter) + 128 syncs
#define BAR_SYNC(id)   asm volatile("bar.sync %0, 256;"   :: "r"(id) : "memory")
#define BAR_ARRIVE(id) asm volatile("bar.arrive %0, 256;" :: "r"(id) : "memory")

#define LDM4(r0, r1, r2, r3, addr) \
    asm volatile("ldmatrix.sync.aligned.m8n8.x4.shared.b16 {%0,%1,%2,%3}, [%4];" \
                 : "=r"(r0), "=r"(r1), "=r"(r2), "=r"(r3) : "r"(addr))
#define LDM4T(r0, r1, r2, r3, addr) \
    asm volatile("ldmatrix.sync.aligned.m8n8.x4.trans.shared.b16 {%0,%1,%2,%3}, [%4];" \
                 : "=r"(r0), "=r"(r1), "=r"(r2), "=r"(r3) : "r"(addr))

#define MMAF(d, a, b0, b1) \
    asm volatile("mma.sync.aligned.m16n8k16.row.col.f32.bf16.bf16.f32 " \
                 "{%0,%1,%2,%3}, {%4,%5,%6,%7}, {%8,%9}, {%0,%1,%2,%3};" \
                 : "+f"((d)[0]), "+f"((d)[1]), "+f"((d)[2]), "+f"((d)[3]) \
                 : "r"((a)[0]), "r"((a)[1]), "r"((a)[2]), "r"((a)[3]), \
                   "r"(b0), "r"(b1))

static __device__ __forceinline__ uint32_t sw(int r, int c) {
    return (uint32_t)(r * 64 + ((c ^ ((r >> 1) & 3)) * 16));
}
static __device__ __forceinline__ uint32_t swz(int r, int c) {
    return (uint32_t)(r * 128 + ((c ^ (r & 7)) * 16));
}

static __device__ __forceinline__ uint32_t pack_bf2(float lo, float hi) {
    __nv_bfloat162 t = __float22bfloat162_rn(make_float2(lo, hi));
    return *(uint32_t*)&t;
}
static __device__ __forceinline__ float2 unpack_bf2(uint32_t u) {
    __nv_bfloat162 t = *(__nv_bfloat162*)&u;
    return __bfloat1622float2(t);
}

// ---------------------------------------------------------------------------
// merged split kernel: 5 regions, block = 1024 elements
// ---------------------------------------------------------------------------
struct SplitArgs {
    const float* src[5];
    __nv_bfloat16* dst[5];
    int n[5];
    int off[5];
};

__global__ __launch_bounds__(256) void split_all_k(SplitArgs a)
{
    int blk = blockIdx.x;
    int r = 0;
    if (blk >= a.off[1]) r = 1;
    if (blk >= a.off[2]) r = 2;
    if (blk >= a.off[3]) r = 3;
    if (blk >= a.off[4]) r = 4;

    const float* X = a.src[r];
    __nv_bfloat16* S = a.dst[r];
    const int n = a.n[r];
    int i = (blk - a.off[r]) * 1024 + threadIdx.x * 4;

    float4 x = *(const float4*)(X + i);
    float v[4] = {x.x, x.y, x.z, x.w};
    __nv_bfloat16 h[4];
    #pragma unroll
    for (int j = 0; j < 4; j++)
        h[j] = __float2bfloat16(v[j]);
    *(__nv_bfloat162*)(S + i)     = __halves2bfloat162(h[0], h[1]);
    *(__nv_bfloat162*)(S + i + 2) = __halves2bfloat162(h[2], h[3]);
    *(__nv_bfloat162*)(S + n + i) = __halves2bfloat162(
        __float2bfloat16(v[0] - __bfloat162float(h[0])),
        __float2bfloat16(v[1] - __bfloat162float(h[1])));
    *(__nv_bfloat162*)(S + n + i + 2) = __halves2bfloat162(
        __float2bfloat16(v[2] - __bfloat162float(h[2])),
        __float2bfloat16(v[3] - __bfloat162float(h[3])));
}

// ---------------------------------------------------------------------------
// Split-bf16 NT GEMM v6: 6-slot ring, distance-2 prefetch, split-barrier
// (named-barrier arrive/wait) pipeline so the last MMA phase overlaps the
// next iteration's rendezvous.  d += Ah*Bh + Al*Bh + Ah*Bl.
// Block 128x128, 4 warps (2m x 2n), warp tile 64x64, BK=32.
// ---------------------------------------------------------------------------
#define G5_SLOT 16384
#define G5_SMEM (6 * G5_SLOT)           // 98304; 2 CTAs/SM

template<int OMODE>
static __device__ __forceinline__ void gemm_body(
    const __nv_bfloat16* __restrict__ A, const __nv_bfloat16* __restrict__ B,
    const float* __restrict__ bias, void* __restrict__ Cv,
    int M, int N, int m0, int n0)
{
    extern __shared__ __align__(1024) char smem[];
    const uint32_t sb = smem_u32(smem);

    const int tid  = threadIdx.x;
    const int wid  = tid >> 5;
    const int lane = tid & 31;
    const int wm   = wid & 1;
    const int wn   = wid >> 1;

    const size_t MK = (size_t)M * HID, NK = (size_t)N * HID;
    const int NKB = 32;

    #define PRE(kb, s) do {                                                   \
        uint32_t _ba = sb + (s) * G5_SLOT;                                    \
        uint32_t _bb = sb + (3 + (s)) * G5_SLOT;                              \
        _Pragma("unroll")                                                     \
        for (int _q = 0; _q < 4; _q++) {                                      \
            int _ch = tid + _q * 128;                                         \
            int _r = _ch >> 2, _c = _ch & 3;                                  \
            const __nv_bfloat16* _pa = A + (size_t)(m0 + _r) * HID + (kb) * 32 + _c * 8; \
            const __nv_bfloat16* _pb = B + (size_t)(n0 + _r) * HID + (kb) * 32 + _c * 8; \
            uint32_t _d = sw(_r, _c);                                         \
            CPA16(_ba + _d, _pa);                                             \
            CPA16(_ba + 8192 + _d, _pa + MK);                                 \
            CPA16(_bb + _d, _pb);                                             \
            CPA16(_bb + 8192 + _d, _pb + NK);                                 \
        }                                                                     \
        CPA_COMMIT();                                                         \
    } while (0)

    float d[4][8][4] = {};

    PRE(0, 0); PRE(1, 1);
    CPA_WAIT1();            // group 0 landed (mine)
    BAR_ARRIVE(1);          // prologue arrive for iter 0's sync

    #pragma unroll 1
    for (int kb = 0; kb < NKB; kb++) {
        BAR_SYNC(1 + (kb & 1));   // all threads' slot-kb data landed+visible

        const int slot = kb % 3;
        const uint32_t ah_base = sb + slot * G5_SLOT;
        const uint32_t al_base = ah_base + 8192;
        const uint32_t bh_base = sb + (3 + slot) * G5_SLOT;
        const uint32_t bl_base = bh_base + 8192;

        #pragma unroll
        for (int ks = 0; ks < 2; ks++) {
            const int ar = wm * 64 + (lane & 15);
            const int ac = ks * 2 + ((lane >> 4) & 1);
            const int br = wn * 64 + ((lane >> 4) & 1) * 8 + (lane & 7);
            const int bc = ks * 2 + ((lane >> 3) & 1);

            uint32_t ah[4][4], bh[8][2];
            #pragma unroll
            for (int mi = 0; mi < 4; mi++)
                LDM4(ah[mi][0], ah[mi][1], ah[mi][2], ah[mi][3],
                     ah_base + sw(ar + mi * 16, ac));
            #pragma unroll
            for (int ni = 0; ni < 4; ni++) {
                uint32_t r0, r1, r2, r3;
                LDM4(r0, r1, r2, r3, bh_base + sw(br + ni * 16, bc));
                bh[ni * 2][0] = r0;     bh[ni * 2][1] = r1;
                bh[ni * 2 + 1][0] = r2; bh[ni * 2 + 1][1] = r3;
            }
            // P1: Ah * Bh
            #pragma unroll
            for (int mi = 0; mi < 4; mi++)
                #pragma unroll
                for (int nj = 0; nj < 8; nj++)
                    MMAF(d[mi][nj], ah[mi], bh[nj][0], bh[nj][1]);

            uint32_t al[4][4], bl[8][2];
            #pragma unroll
            for (int mi = 0; mi < 4; mi++)
                LDM4(al[mi][0], al[mi][1], al[mi][2], al[mi][3],
                     al_base + sw(ar + mi * 16, ac));
            #pragma unroll
            for (int ni = 0; ni < 4; ni++) {
                uint32_t r0, r1, r2, r3;
                LDM4(r0, r1, r2, r3, bl_base + sw(br + ni * 16, bc));
                bl[ni * 2][0] = r0;     bl[ni * 2][1] = r1;
                bl[ni * 2 + 1][0] = r2; bl[ni * 2 + 1][1] = r3;
            }

            if (ks == 1) {
                // all reads of slot kb done; prefetch, certify next slot,
                // arrive — then issue the remaining 64 MMAs.
                if (kb + 2 < NKB) PRE(kb + 2, (kb + 2) % 3);
                if (kb < NKB - 2) CPA_WAIT1(); else CPA_WAIT0();
                BAR_ARRIVE(1 + ((kb + 1) & 1));
            }

            // P3: Al * Bh
            #pragma unroll
            for (int mi = 0; mi < 4; mi++)
                #pragma unroll
                for (int nj = 0; nj < 8; nj++)
                    MMAF(d[mi][nj], al[mi], bh[nj][0], bh[nj][1]);
            // P2: Ah * Bl
            #pragma unroll
            for (int mi = 0; mi < 4; mi++)
                #pragma unroll
                for (int nj = 0; nj < 8; nj++)
                    MMAF(d[mi][nj], ah[mi], bl[nj][0], bl[nj][1]);
        }
    }
    #undef PRE

    const int row0 = m0 + wm * 64 + (lane >> 2);
    const int col0 = n0 + wn * 64 + (lane & 3) * 2;

    if (OMODE == 1) {
        float* C = (float*)Cv;
        #pragma unroll
        for (int mi = 0; mi < 4; mi++) {
            #pragma unroll
            for (int nj = 0; nj < 8; nj++) {
                int r = row0 + mi * 16;
                int cc = col0 + nj * 8;
                float b0 = __ldg(bias + cc), b1 = __ldg(bias + cc + 1);
                *(float2*)(C + (size_t)r * N + cc) =
                    make_float2(d[mi][nj][0] + b0, d[mi][nj][1] + b1);
                *(float2*)(C + (size_t)(r + 8) * N + cc) =
                    make_float2(d[mi][nj][2] + b0, d[mi][nj][3] + b1);
            }
        }
    } else {
        __nv_bfloat16* C = (__nv_bfloat16*)Cv;
        const size_t MN = (size_t)M * N;
        #pragma unroll
        for (int mi = 0; mi < 4; mi++) {
            #pragma unroll
            for (int nj = 0; nj < 8; nj++) {
                int r = row0 + mi * 16;
                int cc = col0 + nj * 8;
                #pragma unroll
                for (int half = 0; half < 2; half++) {
                    float v0 = d[mi][nj][half * 2];
                    float v1 = d[mi][nj][half * 2 + 1];
                    size_t off = (size_t)(r + half * 8) * N + cc;
                    __nv_bfloat16 h0 = __float2bfloat16(v0);
                    __nv_bfloat16 h1 = __float2bfloat16(v1);
                    *(__nv_bfloat162*)(C + off) = __halves2bfloat162(h0, h1);
                    *(__nv_bfloat162*)(C + MN + off) = __halves2bfloat162(
                        __float2bfloat16(v0 - __bfloat162float(h0)),
                        __float2bfloat16(v1 - __bfloat162float(h1)));
                }
            }
        }
    }
}

__global__ __launch_bounds__(128, 2) void gemm_sp(
    const __nv_bfloat16* __restrict__ A, const __nv_bfloat16* __restrict__ B,
    __nv_bfloat16* __restrict__ C, int M, int N)
{
    gemm_body<2>(A, B, nullptr, C, M, N, blockIdx.y * 128, blockIdx.x * 128);
}

__global__ __launch_bounds__(128, 2) void gemm_out(
    const __nv_bfloat16* __restrict__ x, const __nv_bfloat16* __restrict__ wo,
    const float* __restrict__ bias, float* __restrict__ out)
{
    gemm_body<1>(x, wo, bias, out, NB * SQL, HID,
                 blockIdx.y * 128, blockIdx.x * 128);
}

// ---------------------------------------------------------------------------
// Split-bf16 mma.sync flash attention, 3-stage KV ring (unchanged).
// ---------------------------------------------------------------------------
#define AT_SMEM (32768 + 3 * 32768)     // 131072

__global__ __launch_bounds__(256, 1) void attn_mma(
    const __nv_bfloat16* __restrict__ q,
    const __nv_bfloat16* __restrict__ kvs,
    __nv_bfloat16* __restrict__ xout)
{
    extern __shared__ __align__(1024) char smem[];
    const uint32_t sb  = smem_u32(smem);
    const uint32_t sQh = sb, sQl = sb + 16384;

    const int tid  = threadIdx.x;
    const int lane = tid & 31;
    const int w    = tid >> 5;
    const int lr   = lane & 7;
    const int sel  = lane >> 3;

    const int qt = blockIdx.x;
    const int bh = blockIdx.y;
    const int b  = bh >> 4;
    const int h  = bh & 15;

    const size_t NQ  = (size_t)NB * SQL * HID;
    const size_t NKV = (size_t)NB * SKV * 2 * HID;

    const __nv_bfloat16* Qb = q   + (size_t)(b * SQL + qt * 128) * HID + h * HD;
    const __nv_bfloat16* Kb = kvs + (size_t)b * SKV * 2 * HID + h * HD;

    {
        #pragma unroll
        for (int qq = 0; qq < 4; qq++) {
            int ch = tid * 4 + qq;
            int r = ch >> 3, c = ch & 7;
            const __nv_bfloat16* src = Qb + (size_t)r * HID + c * 8;
            CPA16(sQh + swz(r, c), src);
            CPA16(sQl + swz(r, c), src + NQ);
        }
    }
    #define ISSUE_KV(t) do {                                                  \
        int _kv0 = (t) * 64;                                                  \
        uint32_t _st = sb + 32768 + ((t) % 3) * 32768;                        \
        _Pragma("unroll")                                                     \
        for (int _qq = 0; _qq < 2; _qq++) {                                   \
            int _ch = tid * 2 + _qq;                                          \
            int _r = _ch >> 3, _c = _ch & 7;                                  \
            const __nv_bfloat16* _k = Kb + (size_t)(_kv0 + _r) * 2048 + _c * 8; \
            uint32_t _d = swz(_r, _c);                                        \
            CPA16(_st +         _d, _k);                                      \
            CPA16(_st + 8192  + _d, _k + NKV);                                \
            CPA16(_st + 16384 + _d, _k + HID);                                \
            CPA16(_st + 24576 + _d, _k + HID + NKV);                          \
        }                                                                     \
        CPA_COMMIT();                                                         \
    } while (0)

    CPA_COMMIT();           // Q group
    ISSUE_KV(0);
    ISSUE_KV(1);
    CPA_WAIT1();            // Q + KV0 complete
    __syncthreads();

    uint32_t QAh[4][4], QAl[4][4];
    {
        const int r0 = w * 16;
        #pragma unroll
        for (int kk = 0; kk < 4; kk++) {
            int row = r0 + lr + ((sel & 1) ? 8 : 0);
            int ch  = 2 * kk + (sel >> 1);
            LDM4(QAh[kk][0], QAh[kk][1], QAh[kk][2], QAh[kk][3], sQh + swz(row, ch));
            LDM4(QAl[kk][0], QAl[kk][1], QAl[kk][2], QAl[kk][3], sQl + swz(row, ch));
        }
    }

    float O[8][4] = {};
    float m0 = -1e30f, m1 = -1e30f, l0 = 0.f, l1 = 0.f;

    #pragma unroll 1
    for (int kt = 0; kt < 32; kt++) {
        const uint32_t st  = sb + 32768 + (kt % 3) * 32768;
        const uint32_t sKh = st, sKl = st + 8192;
        const uint32_t sVh = st + 16384, sVl = st + 24576;

        float S[8][4];
        #pragma unroll
        for (int g = 0; g < 8; g++)
            S[g][0] = S[g][1] = S[g][2] = S[g][3] = 0.f;

        #pragma unroll
        for (int kk = 0; kk < 4; kk++) {
            uint32_t bk[4][4];
            #pragma unroll
            for (int jp = 0; jp < 4; jp++) {
                int row = jp * 16 + lr + ((sel & 2) ? 8 : 0);
                int ch  = 2 * kk + (sel & 1);
                LDM4(bk[jp][0], bk[jp][1], bk[jp][2], bk[jp][3], sKh + swz(row, ch));
            }
            #pragma unroll
            for (int jp = 0; jp < 4; jp++) {
                MMAF(S[2*jp],   QAh[kk], bk[jp][0], bk[jp][1]);
                MMAF(S[2*jp+1], QAh[kk], bk[jp][2], bk[jp][3]);
                MMAF(S[2*jp],   QAl[kk], bk[jp][0], bk[jp][1]);
                MMAF(S[2*jp+1], QAl[kk], bk[jp][2], bk[jp][3]);
            }
        }
        #pragma unroll
        for (int kk = 0; kk < 4; kk++) {
            uint32_t bk[4][4];
            #pragma unroll
            for (int jp = 0; jp < 4; jp++) {
                int row = jp * 16 + lr + ((sel & 2) ? 8 : 0);
                int ch  = 2 * kk + (sel & 1);
                LDM4(bk[jp][0], bk[jp][1], bk[jp][2], bk[jp][3], sKl + swz(row, ch));
            }
            #pragma unroll
            for (int jp = 0; jp < 4; jp++) {
                MMAF(S[2*jp],   QAh[kk], bk[jp][0], bk[jp][1]);
                MMAF(S[2*jp+1], QAh[kk], bk[jp][2], bk[jp][3]);
            }
        }

        float mx0 = -1e30f, mx1 = -1e30f;
        #pragma unroll
        for (int g = 0; g < 8; g++) {
            S[g][0] *= 0.125f; S[g][1] *= 0.125f;
            S[g][2] *= 0.125f; S[g][3] *= 0.125f;
            mx0 = fmaxf(mx0, fmaxf(S[g][0], S[g][1]));
            mx1 = fmaxf(mx1, fmaxf(S[g][2], S[g][3]));
        }
        mx0 = fmaxf(mx0, __shfl_xor_sync(0xffffffffu, mx0, 1));
        mx0 = fmaxf(mx0, __shfl_xor_sync(0xffffffffu, mx0, 2));
        mx1 = fmaxf(mx1, __shfl_xor_sync(0xffffffffu, mx1, 1));
        mx1 = fmaxf(mx1, __shfl_xor_sync(0xffffffffu, mx1, 2));
        float mn0 = fmaxf(m0, mx0), mn1 = fmaxf(m1, mx1);
        float c0 = __expf(m0 - mn0), c1 = __expf(m1 - mn1);
        float sum0 = 0.f, sum1 = 0.f;
        #pragma unroll
        for (int g = 0; g < 8; g++) {
            S[g][0] = __expf(S[g][0] - mn0);
            S[g][1] = __expf(S[g][1] - mn0);
            S[g][2] = __expf(S[g][2] - mn1);
            S[g][3] = __expf(S[g][3] - mn1);
            sum0 += S[g][0] + S[g][1];
            sum1 += S[g][2] + S[g][3];
        }
        sum0 += __shfl_xor_sync(0xffffffffu, sum0, 1);
        sum0 += __shfl_xor_sync(0xffffffffu, sum0, 2);
        sum1 += __shfl_xor_sync(0xffffffffu, sum1, 1);
        sum1 += __shfl_xor_sync(0xffffffffu, sum1, 2);
        l0 = l0 * c0 + sum0;  l1 = l1 * c1 + sum1;
        m0 = mn0;  m1 = mn1;
        #pragma unroll
        for (int g = 0; g < 8; g++) {
            O[g][0] *= c0; O[g][1] *= c0;
            O[g][2] *= c1; O[g][3] *= c1;
        }

        #pragma unroll
        for (int kk = 0; kk < 4; kk++) {
            uint32_t pah[4], pal[4];
            {
                float* A0 = S[2*kk];
                float* A1 = S[2*kk+1];
                pah[0] = pack_bf2(A0[0], A0[1]);
                pah[1] = pack_bf2(A0[2], A0[3]);
                pah[2] = pack_bf2(A1[0], A1[1]);
                pah[3] = pack_bf2(A1[2], A1[3]);
                float2 f0 = unpack_bf2(pah[0]), f1 = unpack_bf2(pah[1]);
                float2 f2 = unpack_bf2(pah[2]), f3 = unpack_bf2(pah[3]);
                pal[0] = pack_bf2(A0[0] - f0.x, A0[1] - f0.y);
                pal[1] = pack_bf2(A0[2] - f1.x, A0[3] - f1.y);
                pal[2] = pack_bf2(A1[0] - f2.x, A1[1] - f2.y);
                pal[3] = pack_bf2(A1[2] - f3.x, A1[3] - f3.y);
            }
            uint32_t bv[4][4];
            #pragma unroll
            for (int jp = 0; jp < 4; jp++) {
                int row = kk * 16 + lr + ((sel & 1) ? 8 : 0);
                int ch  = 2 * jp + (sel >> 1);
                LDM4T(bv[jp][0], bv[jp][1], bv[jp][2], bv[jp][3], sVh + swz(row, ch));
            }
            #pragma unroll
            for (int jp = 0; jp < 4; jp++) {
                MMAF(O[2*jp],   pah, bv[jp][0], bv[jp][1]);
                MMAF(O[2*jp+1], pah, bv[jp][2], bv[jp][3]);
                MMAF(O[2*jp],   pal, bv[jp][0], bv[jp][1]);
                MMAF(O[2*jp+1], pal, bv[jp][2], bv[jp][3]);
            }
            #pragma unroll
            for (int jp = 0; jp < 4; jp++) {
                int row = kk * 16 + lr + ((sel & 1) ? 8 : 0);
                int ch  = 2 * jp + (sel >> 1);
                LDM4T(bv[jp][0], bv[jp][1], bv[jp][2], bv[jp][3], sVl + swz(row, ch));
            }
            #pragma unroll
            for (int jp = 0; jp < 4; jp++) {
                MMAF(O[2*jp],   pah, bv[jp][0], bv[jp][1]);
                MMAF(O[2*jp+1], pah, bv[jp][2], bv[jp][3]);
            }
        }

        if (kt + 2 < 32) ISSUE_KV(kt + 2);
        if (kt + 1 < 32) {
            if (kt + 2 < 32) CPA_WAIT1(); else CPA_WAIT0();
            __syncthreads();
        }
    }
    #undef ISSUE_KV

    {
        float inv0 = 1.f / l0, inv1 = 1.f / l1;
        int row = b * SQL + qt * 128 + w * 16 + (lane >> 2);
        size_t base = (size_t)row * HID + h * HD + (lane & 3) * 2;
        #pragma unroll
        for (int g = 0; g < 8; g++) {
            float x0 = O[g][0] * inv0, x1 = O[g][1] * inv0;
            float y0 = O[g][2] * inv1, y1 = O[g][3] * inv1;
            __nv_bfloat16 h0 = __float2bfloat16(x0), h1 = __float2bfloat16(x1);
            __nv_bfloat16 g0 = __float2bfloat16(y0), g1 = __float2bfloat16(y1);
            *(__nv_bfloat162*)(xout + base + 8 * g) = __halves2bfloat162(h0, h1);
            *(__nv_bfloat162*)(xout + NQ + base + 8 * g) =
                __halves2bfloat162(__float2bfloat16(x0 - __bfloat162float(h0)),
                                   __float2bfloat16(x1 - __bfloat162float(h1)));
            *(__nv_bfloat162*)(xout + base + 8 * HID + 8 * g) = __halves2bfloat162(g0, g1);
            *(__nv_bfloat162*)(xout + NQ + base + 8 * HID + 8 * g) =
                __halves2bfloat162(__float2bfloat16(y0 - __bfloat162float(g0)),
                                   __float2bfloat16(y1 - __bfloat162float(g1)));
        }
    }
}

// ---------------------------------------------------------------------------
extern "C" void kernel_launch(void* const* d_in, const int* in_sizes, int n_in,
                              void* d_out, int out_size)
{
    const float* xq   = (const float*)d_in[0];
    const float* xkv  = (const float*)d_in[1];
    const float* Wq   = (const float*)d_in[2];
    const float* Wkv  = (const float*)d_in[3];
    const float* Wout = (const float*)d_in[4];
    const float* bout = (const float*)d_in[5];
    float* out = (float*)d_out;

    void *p_xq, *p_xkv, *p_wq, *p_wkv, *p_wo, *p_x, *p_qa, *p_kva;
    cudaGetSymbolAddress(&p_xq,  s_xq);
    cudaGetSymbolAddress(&p_xkv, s_xkv);
    cudaGetSymbolAddress(&p_wq,  s_wq);
    cudaGetSymbolAddress(&p_wkv, s_wkv);
    cudaGetSymbolAddress(&p_wo,  s_wo);
    cudaGetSymbolAddress(&p_x,   s_x);
    cudaGetSymbolAddress(&p_qa,  s_qa);
    cudaGetSymbolAddress(&p_kva, s_kva);

    cudaFuncSetAttribute(attn_mma,
        cudaFuncAttributeMaxDynamicSharedMemorySize, AT_SMEM);
    cudaFuncSetAttribute(gemm_sp,
        cudaFuncAttributeMaxDynamicSharedMemorySize, G5_SMEM);
    cudaFuncSetAttribute(gemm_out,
        cudaFuncAttributeMaxDynamicSharedMemorySize, G5_SMEM);

    // ---- one merged split launch ----
    SplitArgs sa;
    sa.src[0] = xq;   sa.dst[0] = (__nv_bfloat16*)p_xq;  sa.n[0] = NB * SQL * HID;
    sa.src[1] = xkv;  sa.dst[1] = (__nv_bfloat16*)p_xkv; sa.n[1] = NB * SKV * HID;
    sa.src[2] = Wq;   sa.dst[2] = (__nv_bfloat16*)p_wq;  sa.n[2] = HID * HID;
    sa.src[3] = Wkv;  sa.dst[3] = (__nv_bfloat16*)p_wkv; sa.n[3] = 2 * HID * HID;
    sa.src[4] = Wout; sa.dst[4] = (__nv_bfloat16*)p_wo;  sa.n[4] = HID * HID;
    int off = 0;
    for (int r = 0; r < 5; r++) { sa.off[r] = off; off += sa.n[r] / 1024; }
    split_all_k<<<off, 256>>>(sa);

    // ---- q = xq @ Wq^T -> split-bf16 s_qa ----
    gemm_sp<<<dim3(HID / 128, (NB * SQL) / 128), 128, G5_SMEM>>>(
        (const __nv_bfloat16*)p_xq, (const __nv_bfloat16*)p_wq,
        (__nv_bfloat16*)p_qa, NB * SQL, HID);

    // ---- kv = xkv @ Wkv^T -> split-bf16 s_kva ----
    gemm_sp<<<dim3((2 * HID) / 128, (NB * SKV) / 128), 128, G5_SMEM>>>(
        (const __nv_bfloat16*)p_xkv, (const __nv_bfloat16*)p_wkv,
        (__nv_bfloat16*)p_kva, NB * SKV, 2 * HID);

    // ---- attention (writes split-bf16 x directly) ----
    attn_mma<<<dim3(SQL / 128, NB * NH), 256, AT_SMEM>>>(
        (const __nv_bfloat16*)p_qa, (const __nv_bfloat16*)p_kva,
        (__nv_bfloat16*)p_x);

    // ---- out = x @ Wout^T + bout ----
    gemm_out<<<dim3(HID / 128, (NB * SQL) / 128), 128, G5_SMEM>>>(
        (const __nv_bfloat16*)p_x, (const __nv_bfloat16*)p_wo,
        bout, out);
}

// round 12
// speedup vs baseline: 1.0335x; 1.0335x over previous
#include <cuda_runtime.h>
#include <cuda_bf16.h>
#include <math.h>
#include <stdint.h>

#define HID 1024
#define NH  16
#define HD  64
#define NB  4
#define SQL 1024
#define SKV 2048

// q pre-scale: 0.125 * log2(e)  (softmax done in base 2)
#define SCALE_Q 0.18033688011112042f

// ---------------- scratch (__device__ globals; no allocs allowed) ----------
__device__ __nv_bfloat16 s_xq [(size_t)2 * NB * SQL * HID];
__device__ __nv_bfloat16 s_xkv[(size_t)2 * NB * SKV * HID];
__device__ __nv_bfloat16 s_wq [(size_t)2 * HID * HID];
__device__ __nv_bfloat16 s_wkv[(size_t)2 * 2 * HID * HID];
__device__ __nv_bfloat16 s_wo [(size_t)2 * HID * HID];
__device__ __nv_bfloat16 s_x  [(size_t)2 * NB * SQL * HID];
__device__ __nv_bfloat16 s_qa [(size_t)2 * NB * SQL * HID];
__device__ __nv_bfloat16 s_kva[(size_t)2 * NB * SKV * 2 * HID];

// ---------------------------------------------------------------------------
static __device__ __forceinline__ uint32_t smem_u32(const void* p) {
    uint32_t a;
    asm("{ .reg .u64 t; cvta.to.shared.u64 t, %1; cvt.u32.u64 %0, t; }"
        : "=r"(a) : "l"(p));
    return a;
}
static __device__ __forceinline__ float ex2f(float x) {
    float r;
    asm("ex2.approx.f32 %0, %1;" : "=f"(r) : "f"(x));
    return r;
}

#define CPA16(dst, src) \
    asm volatile("cp.async.cg.shared.global [%0], [%1], 16;" \
                 :: "r"(dst), "l"(src) : "memory")
#define CPA_COMMIT() asm volatile("cp.async.commit_group;" ::: "memory")
#define CPA_WAIT1()  asm volatile("cp.async.wait_group 1;" ::: "memory")
#define CPA_WAIT0()  asm volatile("cp.async.wait_group 0;" ::: "memory")

#define LDM4(r0, r1, r2, r3, addr) \
    asm volatile("ldmatrix.sync.aligned.m8n8.x4.shared.b16 {%0,%1,%2,%3}, [%4];" \
                 : "=r"(r0), "=r"(r1), "=r"(r2), "=r"(r3) : "r"(addr))
#define LDM4T(r0, r1, r2, r3, addr) \
    asm volatile("ldmatrix.sync.aligned.m8n8.x4.trans.shared.b16 {%0,%1,%2,%3}, [%4];" \
                 : "=r"(r0), "=r"(r1), "=r"(r2), "=r"(r3) : "r"(addr))

#define MMAF(d, a, b0, b1) \
    asm volatile("mma.sync.aligned.m16n8k16.row.col.f32.bf16.bf16.f32 " \
                 "{%0,%1,%2,%3}, {%4,%5,%6,%7}, {%8,%9}, {%0,%1,%2,%3};" \
                 : "+f"((d)[0]), "+f"((d)[1]), "+f"((d)[2]), "+f"((d)[3]) \
                 : "r"((a)[0]), "r"((a)[1]), "r"((a)[2]), "r"((a)[3]), \
                   "r"(b0), "r"(b1))

static __device__ __forceinline__ uint32_t sw(int r, int c) {
    return (uint32_t)(r * 64 + ((c ^ ((r >> 1) & 3)) * 16));
}
static __device__ __forceinline__ uint32_t swz(int r, int c) {
    return (uint32_t)(r * 128 + ((c ^ (r & 7)) * 16));
}

static __device__ __forceinline__ uint32_t pack_bf2(float lo, float hi) {
    __nv_bfloat162 t = __float22bfloat162_rn(make_float2(lo, hi));
    return *(uint32_t*)&t;
}
static __device__ __forceinline__ float2 unpack_bf2(uint32_t u) {
    __nv_bfloat162 t = *(__nv_bfloat162*)&u;
    return __bfloat1622float2(t);
}

// ---------------------------------------------------------------------------
// split fp32 -> (hi, lo) bf16   (R9 layout: 5 separate launches)
// ---------------------------------------------------------------------------
__global__ void split_bf16_k(const float* __restrict__ X,
                             __nv_bfloat16* __restrict__ S, int n)
{
    int i = (blockIdx.x * blockDim.x + threadIdx.x) * 4;
    if (i >= n) return;
    float4 x = *(const float4*)(X + i);
    float v[4] = {x.x, x.y, x.z, x.w};
    __nv_bfloat16 h[4], l[4];
    #pragma unroll
    for (int j = 0; j < 4; j++) {
        h[j] = __float2bfloat16(v[j]);
        l[j] = __float2bfloat16(v[j] - __bfloat162float(h[j]));
    }
    *(__nv_bfloat162*)(S + i)         = __halves2bfloat162(h[0], h[1]);
    *(__nv_bfloat162*)(S + i + 2)     = __halves2bfloat162(h[2], h[3]);
    *(__nv_bfloat162*)(S + n + i)     = __halves2bfloat162(l[0], l[1]);
    *(__nv_bfloat162*)(S + n + i + 2) = __halves2bfloat162(l[2], l[3]);
}

// ---------------------------------------------------------------------------
// Split-bf16 NT GEMM (R9 gemm_mma5, verbatim except optional output scale).
// ---------------------------------------------------------------------------
#define G5_SLOT 16384
#define G5_SMEM (6 * G5_SLOT)

template<int OMODE>
__global__ __launch_bounds__(128, 2) void gemm_mma5(
    const __nv_bfloat16* __restrict__ A, const __nv_bfloat16* __restrict__ B,
    const float* __restrict__ bias, void* __restrict__ Cv, int M, int N,
    float oscale)
{
    extern __shared__ __align__(1024) char smem[];
    const uint32_t sb = smem_u32(smem);

    const int tid  = threadIdx.x;
    const int wid  = tid >> 5;
    const int lane = tid & 31;
    const int m0   = blockIdx.y * 128;
    const int n0   = blockIdx.x * 128;
    const int wm   = wid & 1;
    const int wn   = wid >> 1;

    const size_t MK = (size_t)M * HID, NK = (size_t)N * HID;
    const int NKB = 32;

    #define PRE_A(kb, s) do {                                                 \
        uint32_t _ba = sb + (s) * G5_SLOT;                                    \
        _Pragma("unroll")                                                     \
        for (int _q = 0; _q < 4; _q++) {                                      \
            int _ch = tid + _q * 128;                                         \
            int _r = _ch >> 2, _c = _ch & 3;                                  \
            const __nv_bfloat16* _p = A + (size_t)(m0 + _r) * HID + (kb) * 32 + _c * 8; \
            CPA16(_ba + sw(_r, _c), _p);                                      \
            CPA16(_ba + 8192 + sw(_r, _c), _p + MK);                          \
        }                                                                     \
        CPA_COMMIT();                                                         \
    } while (0)
    #define PRE_B(kb, s) do {                                                 \
        uint32_t _ba = sb + (3 + (s)) * G5_SLOT;                              \
        _Pragma("unroll")                                                     \
        for (int _q = 0; _q < 4; _q++) {                                      \
            int _ch = tid + _q * 128;                                         \
            int _r = _ch >> 2, _c = _ch & 3;                                  \
            const __nv_bfloat16* _p = B + (size_t)(n0 + _r) * HID + (kb) * 32 + _c * 8; \
            CPA16(_ba + sw(_r, _c), _p);                                      \
            CPA16(_ba + 8192 + sw(_r, _c), _p + NK);                          \
        }                                                                     \
        CPA_COMMIT();                                                         \
    } while (0)

    float d[4][8][4] = {};

    PRE_A(0, 0); PRE_B(0, 0); PRE_A(1, 1); PRE_B(1, 1);

    #pragma unroll 1
    for (int kb = 0; kb < NKB; kb++) {
        if (kb < NKB - 1) CPA_WAIT1(); else CPA_WAIT0();
        __syncthreads();

        const int slot = kb % 3;
        const uint32_t ah_base = sb + slot * G5_SLOT;
        const uint32_t al_base = ah_base + 8192;
        const uint32_t bh_base = sb + (3 + slot) * G5_SLOT;
        const uint32_t bl_base = bh_base + 8192;

        #pragma unroll
        for (int ks = 0; ks < 2; ks++) {
            const int ar = wm * 64 + (lane & 15);
            const int ac = ks * 2 + ((lane >> 4) & 1);
            const int br = wn * 64 + ((lane >> 4) & 1) * 8 + (lane & 7);
            const int bc = ks * 2 + ((lane >> 3) & 1);

            uint32_t ah[4][4], bh[8][2];
            #pragma unroll
            for (int mi = 0; mi < 4; mi++)
                LDM4(ah[mi][0], ah[mi][1], ah[mi][2], ah[mi][3],
                     ah_base + sw(ar + mi * 16, ac));
            #pragma unroll
            for (int ni = 0; ni < 4; ni++) {
                uint32_t r0, r1, r2, r3;
                LDM4(r0, r1, r2, r3, bh_base + sw(br + ni * 16, bc));
                bh[ni * 2][0] = r0;     bh[ni * 2][1] = r1;
                bh[ni * 2 + 1][0] = r2; bh[ni * 2 + 1][1] = r3;
            }
            #pragma unroll
            for (int mi = 0; mi < 4; mi++)
                #pragma unroll
                for (int nj = 0; nj < 8; nj++)
                    MMAF(d[mi][nj], ah[mi], bh[nj][0], bh[nj][1]);

            {
                uint32_t al[4][4];
                #pragma unroll
                for (int mi = 0; mi < 4; mi++)
                    LDM4(al[mi][0], al[mi][1], al[mi][2], al[mi][3],
                         al_base + sw(ar + mi * 16, ac));
                #pragma unroll
                for (int mi = 0; mi < 4; mi++)
                    #pragma unroll
                    for (int nj = 0; nj < 8; nj++)
                        MMAF(d[mi][nj], al[mi], bh[nj][0], bh[nj][1]);
            }
            {
                uint32_t bl[8][2];
                #pragma unroll
                for (int ni = 0; ni < 4; ni++) {
                    uint32_t r0, r1, r2, r3;
                    LDM4(r0, r1, r2, r3, bl_base + sw(br + ni * 16, bc));
                    bl[ni * 2][0] = r0;     bl[ni * 2][1] = r1;
                    bl[ni * 2 + 1][0] = r2; bl[ni * 2 + 1][1] = r3;
                }
                #pragma unroll
                for (int mi = 0; mi < 4; mi++)
                    #pragma unroll
                    for (int nj = 0; nj < 8; nj++)
                        MMAF(d[mi][nj], ah[mi], bl[nj][0], bl[nj][1]);
            }
        }

        if (kb + 2 < NKB) {
            PRE_A(kb + 2, (kb + 2) % 3);
            PRE_B(kb + 2, (kb + 2) % 3);
        }
    }
    #undef PRE_A
    #undef PRE_B

    const int row0 = m0 + wm * 64 + (lane >> 2);
    const int col0 = n0 + wn * 64 + (lane & 3) * 2;

    if (OMODE == 1) {
        float* C = (float*)Cv;
        #pragma unroll
        for (int mi = 0; mi < 4; mi++) {
            #pragma unroll
            for (int nj = 0; nj < 8; nj++) {
                int r = row0 + mi * 16;
                int cc = col0 + nj * 8;
                float b0 = __ldg(bias + cc), b1 = __ldg(bias + cc + 1);
                *(float2*)(C + (size_t)r * N + cc) =
                    make_float2(d[mi][nj][0] + b0, d[mi][nj][1] + b1);
                *(float2*)(C + (size_t)(r + 8) * N + cc) =
                    make_float2(d[mi][nj][2] + b0, d[mi][nj][3] + b1);
            }
        }
    } else {
        __nv_bfloat16* C = (__nv_bfloat16*)Cv;
        const size_t MN = (size_t)M * N;
        #pragma unroll
        for (int mi = 0; mi < 4; mi++) {
            #pragma unroll
            for (int nj = 0; nj < 8; nj++) {
                int r = row0 + mi * 16;
                int cc = col0 + nj * 8;
                #pragma unroll
                for (int half = 0; half < 2; half++) {
                    float v0 = d[mi][nj][half * 2] * oscale;
                    float v1 = d[mi][nj][half * 2 + 1] * oscale;
                    size_t off = (size_t)(r + half * 8) * N + cc;
                    __nv_bfloat16 h0 = __float2bfloat16(v0);
                    __nv_bfloat16 h1 = __float2bfloat16(v1);
                    *(__nv_bfloat162*)(C + off) = __halves2bfloat162(h0, h1);
                    *(__nv_bfloat162*)(C + MN + off) = __halves2bfloat162(
                        __float2bfloat16(v0 - __bfloat162float(h0)),
                        __float2bfloat16(v1 - __bfloat162float(h1)));
                }
            }
        }
    }
}

// ---------------------------------------------------------------------------
// Split-bf16 mma.sync flash attention, 3-stage KV ring, S double-buffered:
// QK(kt+1) issued BEFORE softmax(kt) so tensor work executes while the warp
// issues softmax MUFU/FMA.  Softmax in base 2 (scale folded into q).
// ---------------------------------------------------------------------------
#define AT_SMEM (32768 + 3 * 32768)     // 131072

__global__ __launch_bounds__(256, 1) void attn_mma(
    const __nv_bfloat16* __restrict__ q,
    const __nv_bfloat16* __restrict__ kvs,
    __nv_bfloat16* __restrict__ xout)
{
    extern __shared__ __align__(1024) char smem[];
    const uint32_t sb  = smem_u32(smem);
    const uint32_t sQh = sb, sQl = sb + 16384;

    const int tid  = threadIdx.x;
    const int lane = tid & 31;
    const int w    = tid >> 5;
    const int lr   = lane & 7;
    const int sel  = lane >> 3;

    const int qt = blockIdx.x;
    const int bh = blockIdx.y;
    const int b  = bh >> 4;
    const int h  = bh & 15;

    const size_t NQ  = (size_t)NB * SQL * HID;
    const size_t NKV = (size_t)NB * SKV * 2 * HID;

    const __nv_bfloat16* Qb = q   + (size_t)(b * SQL + qt * 128) * HID + h * HD;
    const __nv_bfloat16* Kb = kvs + (size_t)b * SKV * 2 * HID + h * HD;

    {
        #pragma unroll
        for (int qq = 0; qq < 4; qq++) {
            int ch = tid * 4 + qq;
            int r = ch >> 3, c = ch & 7;
            const __nv_bfloat16* src = Qb + (size_t)r * HID + c * 8;
            CPA16(sQh + swz(r, c), src);
            CPA16(sQl + swz(r, c), src + NQ);
        }
    }
    #define ISSUE_KV(t) do {                                                  \
        int _kv0 = (t) * 64;                                                  \
        uint32_t _st = sb + 32768 + ((t) % 3) * 32768;                        \
        _Pragma("unroll")                                                     \
        for (int _qq = 0; _qq < 2; _qq++) {                                   \
            int _ch = tid * 2 + _qq;                                          \
            int _r = _ch >> 3, _c = _ch & 7;                                  \
            const __nv_bfloat16* _k = Kb + (size_t)(_kv0 + _r) * 2048 + _c * 8; \
            uint32_t _d = swz(_r, _c);                                        \
            CPA16(_st +         _d, _k);                                      \
            CPA16(_st + 8192  + _d, _k + NKV);                                \
            CPA16(_st + 16384 + _d, _k + HID);                                \
            CPA16(_st + 24576 + _d, _k + HID + NKV);                          \
        }                                                                     \
        CPA_COMMIT();                                                         \
    } while (0)

    // QK of tile (slot base ST) into S (zeroed here)
    #define QK_TILE(ST, S) do {                                               \
        const uint32_t _kh = (ST), _kl = (ST) + 8192;                         \
        _Pragma("unroll")                                                     \
        for (int _g = 0; _g < 8; _g++)                                        \
            (S)[_g][0] = (S)[_g][1] = (S)[_g][2] = (S)[_g][3] = 0.f;          \
        _Pragma("unroll")                                                     \
        for (int _kk = 0; _kk < 4; _kk++) {                                   \
            uint32_t _bk[4][4];                                               \
            _Pragma("unroll")                                                 \
            for (int _jp = 0; _jp < 4; _jp++) {                               \
                int _row = _jp * 16 + lr + ((sel & 2) ? 8 : 0);               \
                int _chn = 2 * _kk + (sel & 1);                               \
                LDM4(_bk[_jp][0], _bk[_jp][1], _bk[_jp][2], _bk[_jp][3],      \
                     _kh + swz(_row, _chn));                                  \
            }                                                                 \
            _Pragma("unroll")                                                 \
            for (int _jp = 0; _jp < 4; _jp++) {                               \
                MMAF((S)[2*_jp],   QAh[_kk], _bk[_jp][0], _bk[_jp][1]);       \
                MMAF((S)[2*_jp+1], QAh[_kk], _bk[_jp][2], _bk[_jp][3]);       \
                MMAF((S)[2*_jp],   QAl[_kk], _bk[_jp][0], _bk[_jp][1]);       \
                MMAF((S)[2*_jp+1], QAl[_kk], _bk[_jp][2], _bk[_jp][3]);       \
            }                                                                 \
        }                                                                     \
        _Pragma("unroll")                                                     \
        for (int _kk = 0; _kk < 4; _kk++) {                                   \
            uint32_t _bk[4][4];                                               \
            _Pragma("unroll")                                                 \
            for (int _jp = 0; _jp < 4; _jp++) {                               \
                int _row = _jp * 16 + lr + ((sel & 2) ? 8 : 0);               \
                int _chn = 2 * _kk + (sel & 1);                               \
                LDM4(_bk[_jp][0], _bk[_jp][1], _bk[_jp][2], _bk[_jp][3],      \
                     _kl + swz(_row, _chn));                                  \
            }                                                                 \
            _Pragma("unroll")                                                 \
            for (int _jp = 0; _jp < 4; _jp++) {                               \
                MMAF((S)[2*_jp],   QAh[_kk], _bk[_jp][0], _bk[_jp][1]);       \
                MMAF((S)[2*_jp+1], QAh[_kk], _bk[_jp][2], _bk[_jp][3]);       \
            }                                                                 \
        }                                                                     \
    } while (0)

    // base-2 online softmax on S (scale already folded into q)
    #define SOFTMAX(S) do {                                                   \
        float _mx0 = -1e30f, _mx1 = -1e30f;                                   \
        _Pragma("unroll")                                                     \
        for (int _g = 0; _g < 8; _g++) {                                      \
            _mx0 = fmaxf(_mx0, fmaxf((S)[_g][0], (S)[_g][1]));                \
            _mx1 = fmaxf(_mx1, fmaxf((S)[_g][2], (S)[_g][3]));                \
        }                                                                     \
        _mx0 = fmaxf(_mx0, __shfl_xor_sync(0xffffffffu, _mx0, 1));            \
        _mx0 = fmaxf(_mx0, __shfl_xor_sync(0xffffffffu, _mx0, 2));            \
        _mx1 = fmaxf(_mx1, __shfl_xor_sync(0xffffffffu, _mx1, 1));            \
        _mx1 = fmaxf(_mx1, __shfl_xor_sync(0xffffffffu, _mx1, 2));            \
        float _mn0 = fmaxf(m0, _mx0), _mn1 = fmaxf(m1, _mx1);                 \
        float _c0 = ex2f(m0 - _mn0), _c1 = ex2f(m1 - _mn1);                   \
        float _s0 = 0.f, _s1 = 0.f;                                           \
        _Pragma("unroll")                                                     \
        for (int _g = 0; _g < 8; _g++) {                                      \
            (S)[_g][0] = ex2f((S)[_g][0] - _mn0);                             \
            (S)[_g][1] = ex2f((S)[_g][1] - _mn0);                             \
            (S)[_g][2] = ex2f((S)[_g][2] - _mn1);                             \
            (S)[_g][3] = ex2f((S)[_g][3] - _mn1);                             \
            _s0 += (S)[_g][0] + (S)[_g][1];                                   \
            _s1 += (S)[_g][2] + (S)[_g][3];                                   \
        }                                                                     \
        _s0 += __shfl_xor_sync(0xffffffffu, _s0, 1);                          \
        _s0 += __shfl_xor_sync(0xffffffffu, _s0, 2);                          \
        _s1 += __shfl_xor_sync(0xffffffffu, _s1, 1);                          \
        _s1 += __shfl_xor_sync(0xffffffffu, _s1, 2);                          \
        l0 = l0 * _c0 + _s0;  l1 = l1 * _c1 + _s1;                            \
        m0 = _mn0;  m1 = _mn1;                                                \
        _Pragma("unroll")                                                     \
        for (int _g = 0; _g < 8; _g++) {                                      \
            O[_g][0] *= _c0; O[_g][1] *= _c0;                                 \
            O[_g][2] *= _c1; O[_g][3] *= _c1;                                 \
        }                                                                     \
    } while (0)

    #define PV_TILE(ST, S) do {                                               \
        const uint32_t _vh = (ST) + 16384, _vl = (ST) + 24576;                \
        _Pragma("unroll")                                                     \
        for (int _kk = 0; _kk < 4; _kk++) {                                   \
            uint32_t _pah[4], _pal[4];                                        \
            {                                                                 \
                float* _A0 = (S)[2*_kk];                                      \
                float* _A1 = (S)[2*_kk+1];                                    \
                _pah[0] = pack_bf2(_A0[0], _A0[1]);                           \
                _pah[1] = pack_bf2(_A0[2], _A0[3]);                           \
                _pah[2] = pack_bf2(_A1[0], _A1[1]);                           \
                _pah[3] = pack_bf2(_A1[2], _A1[3]);                           \
                float2 _f0 = unpack_bf2(_pah[0]), _f1 = unpack_bf2(_pah[1]);  \
                float2 _f2 = unpack_bf2(_pah[2]), _f3 = unpack_bf2(_pah[3]);  \
                _pal[0] = pack_bf2(_A0[0] - _f0.x, _A0[1] - _f0.y);           \
                _pal[1] = pack_bf2(_A0[2] - _f1.x, _A0[3] - _f1.y);           \
                _pal[2] = pack_bf2(_A1[0] - _f2.x, _A1[1] - _f2.y);           \
                _pal[3] = pack_bf2(_A1[2] - _f3.x, _A1[3] - _f3.y);           \
            }                                                                 \
            uint32_t _bv[4][4];                                               \
            _Pragma("unroll")                                                 \
            for (int _jp = 0; _jp < 4; _jp++) {                               \
                int _row = _kk * 16 + lr + ((sel & 1) ? 8 : 0);               \
                int _chn = 2 * _jp + (sel >> 1);                              \
                LDM4T(_bv[_jp][0], _bv[_jp][1], _bv[_jp][2], _bv[_jp][3],     \
                      _vh + swz(_row, _chn));                                 \
            }                                                                 \
            _Pragma("unroll")                                                 \
            for (int _jp = 0; _jp < 4; _jp++) {                               \
                MMAF(O[2*_jp],   _pah, _bv[_jp][0], _bv[_jp][1]);             \
                MMAF(O[2*_jp+1], _pah, _bv[_jp][2], _bv[_jp][3]);             \
                MMAF(O[2*_jp],   _pal, _bv[_jp][0], _bv[_jp][1]);             \
                MMAF(O[2*_jp+1], _pal, _bv[_jp][2], _bv[_jp][3]);             \
            }                                                                 \
            _Pragma("unroll")                                                 \
            for (int _jp = 0; _jp < 4; _jp++) {                               \
                int _row = _kk * 16 + lr + ((sel & 1) ? 8 : 0);               \
                int _chn = 2 * _jp + (sel >> 1);                              \
                LDM4T(_bv[_jp][0], _bv[_jp][1], _bv[_jp][2], _bv[_jp][3],     \
                      _vl + swz(_row, _chn));                                 \
            }                                                                 \
            _Pragma("unroll")                                                 \
            for (int _jp = 0; _jp < 4; _jp++) {                               \
                MMAF(O[2*_jp],   _pah, _bv[_jp][0], _bv[_jp][1]);             \
                MMAF(O[2*_jp+1], _pah, _bv[_jp][2], _bv[_jp][3]);             \
            }                                                                 \
        }                                                                     \
    } while (0)

    // one pipeline step: CUR holds QK(kt); computes QK(kt+1) into NXT first.
    #define ATT_STEP(ktv, CUR, NXT) do {                                      \
        const int _kt = (ktv);                                                \
        if (_kt + 2 < 32) ISSUE_KV(_kt + 2);                                  \
        if (_kt + 1 < 32) {                                                   \
            uint32_t _stn = sb + 32768 + ((_kt + 1) % 3) * 32768;             \
            QK_TILE(_stn, NXT);                                               \
        }                                                                     \
        SOFTMAX(CUR);                                                         \
        {                                                                     \
            uint32_t _stc = sb + 32768 + (_kt % 3) * 32768;                   \
            PV_TILE(_stc, CUR);                                               \
        }                                                                     \
        if (_kt + 2 < 32) CPA_WAIT0();                                        \
        if (_kt + 1 < 32) __syncthreads();                                    \
    } while (0)

    CPA_COMMIT();           // Q group
    ISSUE_KV(0);
    ISSUE_KV(1);
    CPA_WAIT1();            // Q + KV0 landed (mine)
    __syncthreads();        // certify Q + KV0

    uint32_t QAh[4][4], QAl[4][4];
    {
        const int r0 = w * 16;
        #pragma unroll
        for (int kk = 0; kk < 4; kk++) {
            int row = r0 + lr + ((sel & 1) ? 8 : 0);
            int ch  = 2 * kk + (sel >> 1);
            LDM4(QAh[kk][0], QAh[kk][1], QAh[kk][2], QAh[kk][3], sQh + swz(row, ch));
            LDM4(QAl[kk][0], QAl[kk][1], QAl[kk][2], QAl[kk][3], sQl + swz(row, ch));
        }
    }

    float O[8][4] = {};
    float m0 = -1e30f, m1 = -1e30f, l0 = 0.f, l1 = 0.f;
    float Sa[8][4], Sb[8][4];

    // prologue: QK(0) into Sa, then certify KV1
    QK_TILE(sb + 32768, Sa);
    CPA_WAIT0();            // KV1 landed (mine)
    __syncthreads();        // certify KV1 cross-warp

    #pragma unroll 1
    for (int kt2 = 0; kt2 < 16; kt2++) {
        ATT_STEP(2 * kt2,     Sa, Sb);
        ATT_STEP(2 * kt2 + 1, Sb, Sa);
    }
    #undef ATT_STEP
    #undef ISSUE_KV

    {
        float inv0 = 1.f / l0, inv1 = 1.f / l1;
        int row = b * SQL + qt * 128 + w * 16 + (lane >> 2);
        size_t base = (size_t)row * HID + h * HD + (lane & 3) * 2;
        #pragma unroll
        for (int g = 0; g < 8; g++) {
            float x0 = O[g][0] * inv0, x1 = O[g][1] * inv0;
            float y0 = O[g][2] * inv1, y1 = O[g][3] * inv1;
            __nv_bfloat16 h0 = __float2bfloat16(x0), h1 = __float2bfloat16(x1);
            __nv_bfloat16 g0 = __float2bfloat16(y0), g1 = __float2bfloat16(y1);
            *(__nv_bfloat162*)(xout + base + 8 * g) = __halves2bfloat162(h0, h1);
            *(__nv_bfloat162*)(xout + NQ + base + 8 * g) =
                __halves2bfloat162(__float2bfloat16(x0 - __bfloat162float(h0)),
                                   __float2bfloat16(x1 - __bfloat162float(h1)));
            *(__nv_bfloat162*)(xout + base + 8 * HID + 8 * g) = __halves2bfloat162(g0, g1);
            *(__nv_bfloat162*)(xout + NQ + base + 8 * HID + 8 * g) =
                __halves2bfloat162(__float2bfloat16(y0 - __bfloat162float(g0)),
                                   __float2bfloat16(y1 - __bfloat162float(g1)));
        }
    }
}

// ---------------------------------------------------------------------------
extern "C" void kernel_launch(void* const* d_in, const int* in_sizes, int n_in,
                              void* d_out, int out_size)
{
    const float* xq   = (const float*)d_in[0];
    const float* xkv  = (const float*)d_in[1];
    const float* Wq   = (const float*)d_in[2];
    const float* Wkv  = (const float*)d_in[3];
    const float* Wout = (const float*)d_in[4];
    const float* bout = (const float*)d_in[5];
    float* out = (float*)d_out;

    void *p_xq, *p_xkv, *p_wq, *p_wkv, *p_wo, *p_x, *p_qa, *p_kva;
    cudaGetSymbolAddress(&p_xq,  s_xq);
    cudaGetSymbolAddress(&p_xkv, s_xkv);
    cudaGetSymbolAddress(&p_wq,  s_wq);
    cudaGetSymbolAddress(&p_wkv, s_wkv);
    cudaGetSymbolAddress(&p_wo,  s_wo);
    cudaGetSymbolAddress(&p_x,   s_x);
    cudaGetSymbolAddress(&p_qa,  s_qa);
    cudaGetSymbolAddress(&p_kva, s_kva);

    cudaFuncSetAttribute(attn_mma,
        cudaFuncAttributeMaxDynamicSharedMemorySize, AT_SMEM);
    cudaFuncSetAttribute(gemm_mma5<1>,
        cudaFuncAttributeMaxDynamicSharedMemorySize, G5_SMEM);
    cudaFuncSetAttribute(gemm_mma5<2>,
        cudaFuncAttributeMaxDynamicSharedMemorySize, G5_SMEM);

    auto sp = [](const float* X, void* S, int n) {
        split_bf16_k<<<(n / 4 + 255) / 256, 256>>>(X, (__nv_bfloat16*)S, n);
    };
    sp(xq,   p_xq,  NB * SQL * HID);
    sp(xkv,  p_xkv, NB * SKV * HID);
    sp(Wq,   p_wq,  HID * HID);
    sp(Wkv,  p_wkv, 2 * HID * HID);
    sp(Wout, p_wo,  HID * HID);

    // q = xq @ Wq^T  -> split-bf16 s_qa, pre-scaled by 0.125*log2(e)
    gemm_mma5<2><<<dim3(HID / 128, (NB * SQL) / 128), 128, G5_SMEM>>>(
        (const __nv_bfloat16*)p_xq, (const __nv_bfloat16*)p_wq,
        nullptr, p_qa, NB * SQL, HID, SCALE_Q);

    // kv = xkv @ Wkv^T -> split-bf16 s_kva
    gemm_mma5<2><<<dim3((2 * HID) / 128, (NB * SKV) / 128), 128, G5_SMEM>>>(
        (const __nv_bfloat16*)p_xkv, (const __nv_bfloat16*)p_wkv,
        nullptr, p_kva, NB * SKV, 2 * HID, 1.0f);

    // attention (writes split-bf16 x directly)
    attn_mma<<<dim3(SQL / 128, NB * NH), 256, AT_SMEM>>>(
        (const __nv_bfloat16*)p_qa, (const __nv_bfloat16*)p_kva,
        (__nv_bfloat16*)p_x);

    // out = x @ Wout^T + bout
    gemm_mma5<1><<<dim3(HID / 128, (NB * SQL) / 128), 128, G5_SMEM>>>(
        (const __nv_bfloat16*)p_x, (const __nv_bfloat16*)p_wo,
        bout, out, NB * SQL, HID, 1.0f);
}